// round 6
// baseline (speedup 1.0000x reference)
#include <cuda_runtime.h>

// ChamferLoss: f[4,8192,3], f_[4,8192,3] -> scalar.
// R6: compute each distance ONCE: h_ij = (||p_j||^2 + ||s_i||^2) - 2 s_i.p_j.
// Row-mins (f -> f_) kept in registers; col-mins (f_ -> f) via per-thread
// candidates -> smem window buffer -> block partial -> global chunk partials.
// Final: small reduce kernels. Halves pair count vs R5 (268M instead of 536M).

namespace {
constexpr int kB = 4;
constexpr int kN = 8192;
constexpr int kThreads = 256;
constexpr int kSrcPerThread = 2;
constexpr int kSrcPerBlock = kThreads * kSrcPerThread;  // 512
constexpr int kChunks = kN / kSrcPerBlock;              // 16
constexpr int kHalves = 2;                              // dst split
constexpr int kDstBlk = kN / kHalves;                   // 4096 dst per block
constexpr int kTile = 2048;                             // dst per smem tile
constexpr int kPairs = kTile / 2;                       // 1024 packed dst pairs
constexpr int kTilesBlk = kDstBlk / kTile;              // 2
constexpr int kWin = 64;                                // jp window for col reduce
constexpr int kWinPerTile = kPairs / kWin;              // 16
constexpr int kBlocks = kChunks * kHalves * kB;         // 128
constexpr int kCandStride = kThreads + 1;               // 257 (pad)
constexpr float kBig = 3.4e38f;

constexpr int kSmemBytes =
    kPairs * 16 * 2 +                     // sA + sB
    kWin * kCandStride * 8 +              // scand
    128 * 4;                              // spart
}  // namespace

__device__ float g_row[kB * kHalves * kN];   // [b][half][src]
__device__ float g_col[kB * kChunks * kN];   // [b][chunk][dst]
__device__ float g_pblk[kBlocks];

__device__ __forceinline__ unsigned long long pack2(float lo, float hi) {
    unsigned long long r;
    asm("mov.b64 %0, {%1, %2};" : "=l"(r) : "f"(lo), "f"(hi));
    return r;
}
__device__ __forceinline__ void unpack2(unsigned long long v, float& lo, float& hi) {
    asm("mov.b64 {%0, %1}, %2;" : "=f"(lo), "=f"(hi) : "l"(v));
}
__device__ __forceinline__ unsigned long long fma2(unsigned long long a, unsigned long long b,
                                                   unsigned long long c) {
    unsigned long long d;
    asm("fma.rn.f32x2 %0, %1, %2, %3;" : "=l"(d) : "l"(a), "l"(b), "l"(c));
    return d;
}
__device__ __forceinline__ unsigned long long add2(unsigned long long a, unsigned long long b) {
    unsigned long long d;
    asm("add.rn.f32x2 %0, %1, %2;" : "=l"(d) : "l"(a), "l"(b));
    return d;
}

__global__ void __launch_bounds__(kThreads, 1)
chamfer_pairs_kernel(const float* __restrict__ f, const float* __restrict__ f_) {
    extern __shared__ char smem[];
    ulonglong2* sA = reinterpret_cast<ulonglong2*>(smem);
    ulonglong2* sB = sA + kPairs;
    unsigned long long* scand = reinterpret_cast<unsigned long long*>(sB + kPairs);
    float* spart = reinterpret_cast<float*>(scand + kWin * kCandStride);

    const int c = blockIdx.x;   // src chunk
    const int h = blockIdx.y;   // dst half
    const int b = blockIdx.z;   // batch

    const float* fp = f + (size_t)b * kN * 3;   // src = f rows
    const float* gp = f_ + (size_t)b * kN * 3;  // dst = f_ cols

    const int tid = threadIdx.x;

    // Src points: replicated packs + packed s^2.
    unsigned long long sxx[kSrcPerThread], syy[kSrcPerThread], szz[kSrcPerThread];
    unsigned long long s2p[kSrcPerThread];
    float m0[kSrcPerThread], m1[kSrcPerThread];
#pragma unroll
    for (int i = 0; i < kSrcPerThread; ++i) {
        const int n = c * kSrcPerBlock + i * kThreads + tid;
        const float x = fp[n * 3 + 0];
        const float y = fp[n * 3 + 1];
        const float z = fp[n * 3 + 2];
        sxx[i] = pack2(x, x);
        syy[i] = pack2(y, y);
        szz[i] = pack2(z, z);
        const float s2 = fmaf(z, z, fmaf(y, y, x * x));
        s2p[i] = pack2(s2, s2);
        m0[i] = kBig;
        m1[i] = kBig;
    }

    for (int t = 0; t < kTilesBlk; ++t) {
        // Fill dst tile: (-2x,-2y),(-2z,w) packed pairs.
        const float* dt = gp + (size_t)(h * kDstBlk + t * kTile) * 3;
        for (int jp = tid; jp < kPairs; jp += kThreads) {
            const float x0 = dt[jp * 6 + 0];
            const float y0 = dt[jp * 6 + 1];
            const float z0 = dt[jp * 6 + 2];
            const float x1 = dt[jp * 6 + 3];
            const float y1 = dt[jp * 6 + 4];
            const float z1 = dt[jp * 6 + 5];
            const float w0 = fmaf(z0, z0, fmaf(y0, y0, x0 * x0));
            const float w1 = fmaf(z1, z1, fmaf(y1, y1, x1 * x1));
            sA[jp] = make_ulonglong2(pack2(-2.0f * x0, -2.0f * x1),
                                     pack2(-2.0f * y0, -2.0f * y1));
            sB[jp] = make_ulonglong2(pack2(-2.0f * z0, -2.0f * z1),
                                     pack2(w0, w1));
        }
        __syncthreads();

        for (int w0i = 0; w0i < kWinPerTile; ++w0i) {
#pragma unroll 4
            for (int jpw = 0; jpw < kWin; ++jpw) {
                const int jp = w0i * kWin + jpw;
                const ulonglong2 A = sA[jp];
                const ulonglong2 B = sB[jp];
                float cand0, cand1;
#pragma unroll
                for (int i = 0; i < kSrcPerThread; ++i) {
                    unsigned long long cc = add2(B.y, s2p[i]);   // w + s2
                    cc = fma2(A.x, sxx[i], cc);
                    cc = fma2(A.y, syy[i], cc);
                    cc = fma2(B.x, szz[i], cc);
                    float h0, h1;
                    unpack2(cc, h0, h1);
                    m0[i] = fminf(m0[i], h0);
                    m1[i] = fminf(m1[i], h1);
                    if (i == 0) { cand0 = h0; cand1 = h1; }
                    else { cand0 = fminf(cand0, h0); cand1 = fminf(cand1, h1); }
                }
                scand[jpw * kCandStride + tid] = pack2(cand0, cand1);
            }
            __syncthreads();

            // Column reduce: 256 tasks: (jpw, half, sub), each sub reduces 128.
            {
                const int jpw = tid >> 2;
                const int half = (tid >> 1) & 1;
                const int sub = tid & 1;
                const float* rf =
                    reinterpret_cast<const float*>(scand + jpw * kCandStride + sub * 128) + half;
                float a0 = kBig, a1 = kBig, a2 = kBig, a3 = kBig;
#pragma unroll 8
                for (int k = 0; k < 128; k += 4) {
                    a0 = fminf(a0, rf[2 * k + 0]);
                    a1 = fminf(a1, rf[2 * k + 2]);
                    a2 = fminf(a2, rf[2 * k + 4]);
                    a3 = fminf(a3, rf[2 * k + 6]);
                }
                float v = fminf(fminf(a0, a1), fminf(a2, a3));
                if (sub == 1) spart[tid >> 1] = v;
                __syncthreads();
                if (sub == 0) {
                    v = fminf(v, spart[tid >> 1]);
                    const int jpGlobal = t * kPairs + w0i * kWin + jpw;
                    const int j = h * kDstBlk + jpGlobal * 2 + half;
                    g_col[((size_t)b * kChunks + c) * kN + j] = v;
                }
            }
            // Next window's scand writes are ordered by the window's first
            // __syncthreads(); but we need one here so sub==0's spart read
            // happens before spart is rewritten. (covered: spart rewritten only
            // after next window's own __syncthreads()) -- still need ordering
            // for scand reuse vs the reduce reads above:
            __syncthreads();
        }
    }

    // Row-min outputs (partial over this dst half).
#pragma unroll
    for (int i = 0; i < kSrcPerThread; ++i) {
        const int n = c * kSrcPerBlock + i * kThreads + tid;
        g_row[((size_t)b * kHalves + h) * kN + n] = fminf(m0[i], m1[i]);
    }
}

// Stage A: 128 blocks x 256 threads. Block k handles row entries and col
// entries [k*256, (k+1)*256); deterministic per-block partial sum.
__global__ void chamfer_reduceA_kernel() {
    __shared__ float swsum[kThreads / 32];
    const int k = blockIdx.x;
    const int tid = threadIdx.x;
    const int e = k * kThreads + tid;  // 0..32767
    const int b = e >> 13;
    const int s = e & (kN - 1);

    const float vr = fminf(g_row[((size_t)b * 2 + 0) * kN + s],
                           g_row[((size_t)b * 2 + 1) * kN + s]);
    float acc = fmaxf(vr, 0.0f);

    float v = kBig;
#pragma unroll
    for (int c = 0; c < kChunks; ++c) {
        v = fminf(v, g_col[((size_t)b * kChunks + c) * kN + s]);
    }
    acc += fmaxf(v, 0.0f);

#pragma unroll
    for (int off = 16; off > 0; off >>= 1) {
        acc += __shfl_xor_sync(0xffffffffu, acc, off);
    }
    if ((tid & 31) == 0) swsum[tid >> 5] = acc;
    __syncthreads();
    if (tid == 0) {
        float t = 0.0f;
#pragma unroll
        for (int w = 0; w < kThreads / 32; ++w) t += swsum[w];
        g_pblk[k] = t;
    }
}

__global__ void chamfer_reduceB_kernel(float* __restrict__ out) {
    __shared__ float sw[4];
    const int tid = threadIdx.x;  // 128
    float v = g_pblk[tid];
#pragma unroll
    for (int off = 16; off > 0; off >>= 1) {
        v += __shfl_xor_sync(0xffffffffu, v, off);
    }
    if ((tid & 31) == 0) sw[tid >> 5] = v;
    __syncthreads();
    if (tid == 0) {
        out[0] = (sw[0] + sw[1] + sw[2] + sw[3]) / (float)(kN * kB);
    }
}

extern "C" void kernel_launch(void* const* d_in, const int* in_sizes, int n_in,
                              void* d_out, int out_size) {
    const float* f = (const float*)d_in[0];
    const float* f_ = (const float*)d_in[1];
    (void)in_sizes; (void)n_in; (void)out_size;

    cudaFuncSetAttribute(chamfer_pairs_kernel,
                         cudaFuncAttributeMaxDynamicSharedMemorySize, kSmemBytes);

    dim3 grid(kChunks, kHalves, kB);
    chamfer_pairs_kernel<<<grid, kThreads, kSmemBytes>>>(f, f_);
    chamfer_reduceA_kernel<<<kBlocks, kThreads>>>();
    chamfer_reduceB_kernel<<<1, 128>>>((float*)d_out);
}